// round 1
// baseline (speedup 1.0000x reference)
#include <cuda_runtime.h>
#include <cuda_bf16.h>

#define NN 50000
#define NE 800000
#define SCAN_B 98          // ceil(50000/512)

// ---------------- scratch (device globals; no allocation allowed) ----------------
__device__ float g_f1[(size_t)NN * 256];   // layer1 projected features
__device__ float g_h1[(size_t)NN * 256];   // layer1 output (post-ELU)
__device__ float g_f2[(size_t)NN * 32];    // layer2 projected features
__device__ float g_el1[NN * 8];
__device__ float g_er1[NN * 8];
__device__ float g_el2[NN];
__device__ float g_er2[NN];
__device__ int   g_offs[NN + 1];
__device__ int   g_cursor[NN];
__device__ int   g_csr_src[NE];
__device__ int   g_partials[SCAN_B + 8];

// ---------------- f32x2 packed-FMA helpers ----------------
__device__ __forceinline__ unsigned long long pk2(float x, float y) {
    unsigned long long r;
    asm("mov.b64 %0, {%1, %2};" : "=l"(r) : "f"(x), "f"(y));
    return r;
}
__device__ __forceinline__ void upk2(unsigned long long v, float& x, float& y) {
    asm("mov.b64 {%0, %1}, %2;" : "=f"(x), "=f"(y) : "l"(v));
}
__device__ __forceinline__ void fma2(unsigned long long& c, unsigned long long a, unsigned long long b) {
    asm("fma.rn.f32x2 %0, %1, %2, %0;" : "+l"(c) : "l"(a), "l"(b));
}

// ---------------- CSR build ----------------
__global__ void k_zero_counts() {
    for (int i = blockIdx.x * blockDim.x + threadIdx.x; i < NN; i += gridDim.x * blockDim.x)
        g_cursor[i] = 0;
}

__global__ void k_degree(const int* __restrict__ dst) {
    for (int e = blockIdx.x * blockDim.x + threadIdx.x; e < NE; e += gridDim.x * blockDim.x)
        atomicAdd(&g_cursor[dst[e]], 1);
}

__global__ void k_scan1() {   // grid SCAN_B, block 512; block-local exclusive scan of g_cursor -> g_offs
    __shared__ int sh[512];
    int t = threadIdx.x;
    int i = blockIdx.x * 512 + t;
    int v = (i < NN) ? g_cursor[i] : 0;
    sh[t] = v;
    __syncthreads();
    #pragma unroll
    for (int o = 1; o < 512; o <<= 1) {
        int add = (t >= o) ? sh[t - o] : 0;
        __syncthreads();
        sh[t] += add;
        __syncthreads();
    }
    if (i < NN) g_offs[i] = sh[t] - v;      // exclusive
    if (t == 511) g_partials[blockIdx.x] = sh[511];
}

__global__ void k_scan2() {   // single thread scans block partials
    if (threadIdx.x == 0 && blockIdx.x == 0) {
        int run = 0;
        for (int i = 0; i < SCAN_B; i++) { int t = g_partials[i]; g_partials[i] = run; run += t; }
    }
}

__global__ void k_scan3() {   // add block prefix; copy into cursor
    int i = blockIdx.x * 512 + threadIdx.x;
    if (i < NN) {
        int v = g_offs[i] + g_partials[blockIdx.x];
        g_offs[i] = v;
        g_cursor[i] = v;
    }
    if (i == 0) g_offs[NN] = NE;
}

__global__ void k_scatter(const int* __restrict__ src, const int* __restrict__ dst) {
    for (int e = blockIdx.x * blockDim.x + threadIdx.x; e < NE; e += gridDim.x * blockDim.x) {
        int p = atomicAdd(&g_cursor[dst[e]], 1);
        g_csr_src[p] = src[e];
    }
}

__global__ void k_sort_buckets() {   // deterministic per-bucket order (sort src ascending)
    int n = blockIdx.x * blockDim.x + threadIdx.x;
    if (n >= NN) return;
    int beg = g_offs[n], end = g_offs[n + 1];
    for (int i = beg + 1; i < end; i++) {
        int key = g_csr_src[i];
        int j = i - 1;
        while (j >= beg && g_csr_src[j] > key) { g_csr_src[j + 1] = g_csr_src[j]; j--; }
        g_csr_src[j + 1] = key;
    }
}

// ---------------- GEMM1: f1[50000,256] = X[50000,128] @ W1[128,256] ----------------
// 128x128 block tile, BK=16, 256 threads, 8x8 per thread via f32x2 packed FMA.
__global__ __launch_bounds__(256) void k_gemm1(const float* __restrict__ A, const float* __restrict__ B) {
    __shared__ float As[16][132];   // transposed [k][m]; 132 keeps float4 rows 16B-aligned
    __shared__ float Bs[16][128];
    int tid = threadIdx.x;
    int tx = tid & 15, ty = tid >> 4;
    int bn = blockIdx.x * 128;
    int bm = blockIdx.y * 128;

    unsigned long long c[8][4];
    #pragma unroll
    for (int i = 0; i < 8; i++)
        #pragma unroll
        for (int j = 0; j < 4; j++) c[i][j] = 0ull;

    for (int kt = 0; kt < 128; kt += 16) {
        #pragma unroll
        for (int j = 0; j < 2; j++) {
            int q = tid + 256 * j;
            int row = q >> 2, c4 = q & 3;
            int gr = bm + row;
            float4 v = make_float4(0.f, 0.f, 0.f, 0.f);
            if (gr < NN) v = *(const float4*)(A + (size_t)gr * 128 + kt + c4 * 4);
            As[c4 * 4 + 0][row] = v.x;
            As[c4 * 4 + 1][row] = v.y;
            As[c4 * 4 + 2][row] = v.z;
            As[c4 * 4 + 3][row] = v.w;
        }
        #pragma unroll
        for (int j = 0; j < 2; j++) {
            int q = tid + 256 * j;
            int kr = q >> 5, c4 = q & 31;
            *(float4*)&Bs[kr][c4 * 4] = *(const float4*)(B + (size_t)(kt + kr) * 256 + bn + c4 * 4);
        }
        __syncthreads();
        #pragma unroll
        for (int k = 0; k < 16; k++) {
            float4 a0 = *(const float4*)&As[k][ty * 4];
            float4 a1 = *(const float4*)&As[k][64 + ty * 4];
            float4 b0 = *(const float4*)&Bs[k][tx * 4];
            float4 b1 = *(const float4*)&Bs[k][64 + tx * 4];
            float av[8] = {a0.x, a0.y, a0.z, a0.w, a1.x, a1.y, a1.z, a1.w};
            unsigned long long bp[4];
            bp[0] = pk2(b0.x, b0.y); bp[1] = pk2(b0.z, b0.w);
            bp[2] = pk2(b1.x, b1.y); bp[3] = pk2(b1.z, b1.w);
            #pragma unroll
            for (int i = 0; i < 8; i++) {
                unsigned long long aa = pk2(av[i], av[i]);
                fma2(c[i][0], aa, bp[0]);
                fma2(c[i][1], aa, bp[1]);
                fma2(c[i][2], aa, bp[2]);
                fma2(c[i][3], aa, bp[3]);
            }
        }
        __syncthreads();
    }
    #pragma unroll
    for (int i = 0; i < 8; i++) {
        int mloc = (i < 4) ? (ty * 4 + i) : (64 + ty * 4 + i - 4);
        int gr = bm + mloc;
        if (gr >= NN) continue;
        float4 lo, hi;
        upk2(c[i][0], lo.x, lo.y); upk2(c[i][1], lo.z, lo.w);
        upk2(c[i][2], hi.x, hi.y); upk2(c[i][3], hi.z, hi.w);
        *(float4*)(g_f1 + (size_t)gr * 256 + bn + tx * 4) = lo;
        *(float4*)(g_f1 + (size_t)gr * 256 + bn + 64 + tx * 4) = hi;
    }
}

// ---------------- layer-1 attention logits: el1/er1 [N,8] ----------------
__global__ __launch_bounds__(256) void k_logits1(const float* __restrict__ al1, const float* __restrict__ ar1) {
    int warp = (blockIdx.x * blockDim.x + threadIdx.x) >> 5;
    int lane = threadIdx.x & 31;
    if (warp >= NN) return;
    const float* f = g_f1 + (size_t)warp * 256;
    #pragma unroll
    for (int h = 0; h < 8; h++) {
        float v = f[h * 32 + lane];
        float pl = v * al1[h * 32 + lane];
        float pr = v * ar1[h * 32 + lane];
        #pragma unroll
        for (int o = 16; o; o >>= 1) {
            pl += __shfl_xor_sync(0xffffffffu, pl, o);
            pr += __shfl_xor_sync(0xffffffffu, pr, o);
        }
        if (lane == 0) { g_el1[warp * 8 + h] = pl; g_er1[warp * 8 + h] = pr; }
    }
}

// ---------------- layer-1 aggregation: softmax over incoming edges + ELU ----------------
__global__ __launch_bounds__(256) void k_agg1(const float* __restrict__ b1) {
    int warp = (blockIdx.x * blockDim.x + threadIdx.x) >> 5;
    int lane = threadIdx.x & 31;
    if (warp >= NN) return;
    int n = warp;
    int beg = g_offs[n], end = g_offs[n + 1];
    int h_own = lane & 7;

    if (beg == end) {   // empty segment: out = elu(0 + b1)
        #pragma unroll
        for (int h = 0; h < 8; h++) {
            float v = b1[h * 32 + lane];
            v = v > 0.f ? v : expm1f(v);
            g_h1[(size_t)n * 256 + h * 32 + lane] = v;
        }
        return;
    }

    float er_own = g_er1[n * 8 + h_own];

    // pass 1: per-head max (4 lanes per head, edges strided by 4)
    float m = -3.402823466e38f;
    for (int i = beg + (lane >> 3); i < end; i += 4) {
        int s = g_csr_src[i];
        float e = g_el1[s * 8 + h_own] + er_own;
        e = e > 0.f ? e : 0.2f * e;
        m = fmaxf(m, e);
    }
    m = fmaxf(m, __shfl_xor_sync(0xffffffffu, m, 8));
    m = fmaxf(m, __shfl_xor_sync(0xffffffffu, m, 16));

    // pass 2: accumulate weighted features; lanes 0..7 own head weights
    float acc[8] = {0.f, 0.f, 0.f, 0.f, 0.f, 0.f, 0.f, 0.f};
    float wsum = 0.f;
    for (int i = beg; i < end; i++) {
        int s = g_csr_src[i];
        float w = 0.f;
        if (lane < 8) {
            float e = g_el1[s * 8 + lane] + er_own;
            e = e > 0.f ? e : 0.2f * e;
            w = __expf(e - m);
            wsum += w;
        }
        const float* fr = g_f1 + (size_t)s * 256;
        #pragma unroll
        for (int h = 0; h < 8; h++) {
            float wh = __shfl_sync(0xffffffffu, w, h);
            acc[h] = fmaf(wh, fr[h * 32 + lane], acc[h]);
        }
    }
    #pragma unroll
    for (int h = 0; h < 8; h++) {
        float d = __shfl_sync(0xffffffffu, wsum, h);
        float v = acc[h] / d + b1[h * 32 + lane];
        v = v > 0.f ? v : expm1f(v);
        g_h1[(size_t)n * 256 + h * 32 + lane] = v;
    }
}

// ---------------- GEMM2 (fused logits): f2[N,32] = h1 @ W2; el2/er2 ----------------
__global__ __launch_bounds__(256) void k_gemm2(const float* __restrict__ W2,
                                               const float* __restrict__ al2,
                                               const float* __restrict__ ar2) {
    __shared__ float4 sW[64][32];   // sW[k4][c] = W2[(4k4+j)*32 + c]
    __shared__ float sal[32], sar[32];
    int tid = threadIdx.x;
    for (int q = tid; q < 2048; q += 256) {
        int k4 = q >> 5, cc = q & 31;
        sW[k4][cc] = make_float4(W2[(k4 * 4 + 0) * 32 + cc], W2[(k4 * 4 + 1) * 32 + cc],
                                 W2[(k4 * 4 + 2) * 32 + cc], W2[(k4 * 4 + 3) * 32 + cc]);
    }
    if (tid < 32) { sal[tid] = al2[tid]; sar[tid] = ar2[tid]; }
    __syncthreads();

    int lane = tid & 31;
    int warp = (blockIdx.x * blockDim.x + tid) >> 5;
    int nwarps = (gridDim.x * blockDim.x) >> 5;
    for (int n = warp; n < NN; n += nwarps) {
        const float4* hrow = (const float4*)(g_h1 + (size_t)n * 256);
        float acc = 0.f;
        #pragma unroll 8
        for (int k4 = 0; k4 < 64; k4++) {
            float4 hv = hrow[k4];                 // broadcast load
            float4 wv = sW[k4][lane];             // conflict-free LDS.128
            acc = fmaf(hv.x, wv.x, acc);
            acc = fmaf(hv.y, wv.y, acc);
            acc = fmaf(hv.z, wv.z, acc);
            acc = fmaf(hv.w, wv.w, acc);
        }
        g_f2[(size_t)n * 32 + lane] = acc;
        float pl = acc * sal[lane];
        float pr = acc * sar[lane];
        #pragma unroll
        for (int o = 16; o; o >>= 1) {
            pl += __shfl_xor_sync(0xffffffffu, pl, o);
            pr += __shfl_xor_sync(0xffffffffu, pr, o);
        }
        if (lane == 0) { g_el2[n] = pl; g_er2[n] = pr; }
    }
}

// ---------------- layer-2 aggregation -> final output [N,32] ----------------
__global__ __launch_bounds__(256) void k_agg2(const float* __restrict__ b2, float* __restrict__ out) {
    int warp = (blockIdx.x * blockDim.x + threadIdx.x) >> 5;
    int lane = threadIdx.x & 31;
    if (warp >= NN) return;
    int n = warp;
    int beg = g_offs[n], end = g_offs[n + 1];
    float bb = b2[lane];
    if (beg == end) { out[(size_t)n * 32 + lane] = bb; return; }

    float er_own = g_er2[n];
    float m = -3.402823466e38f;
    for (int i = beg + lane; i < end; i += 32) {
        int s = g_csr_src[i];
        float e = g_el2[s] + er_own;
        e = e > 0.f ? e : 0.2f * e;
        m = fmaxf(m, e);
    }
    #pragma unroll
    for (int o = 16; o; o >>= 1) m = fmaxf(m, __shfl_xor_sync(0xffffffffu, m, o));

    float acc = 0.f, wsum = 0.f;
    for (int i = beg; i < end; i++) {
        int s = g_csr_src[i];
        float e = g_el2[s] + er_own;
        e = e > 0.f ? e : 0.2f * e;
        float w = __expf(e - m);
        wsum += w;
        acc = fmaf(w, g_f2[(size_t)s * 32 + lane], acc);
    }
    out[(size_t)n * 32 + lane] = acc / wsum + bb;
}

// ---------------- launch ----------------
extern "C" void kernel_launch(void* const* d_in, const int* in_sizes, int n_in,
                              void* d_out, int out_size) {
    const float* x   = (const float*)d_in[0];
    const int*   src = (const int*)d_in[1];
    const int*   dst = (const int*)d_in[2];
    const float* W1  = (const float*)d_in[3];
    const float* al1 = (const float*)d_in[4];
    const float* ar1 = (const float*)d_in[5];
    const float* b1  = (const float*)d_in[6];
    const float* W2  = (const float*)d_in[7];
    const float* al2 = (const float*)d_in[8];
    const float* ar2 = (const float*)d_in[9];
    const float* b2  = (const float*)d_in[10];
    float* out = (float*)d_out;

    // CSR build (deterministic: per-bucket sorted by src)
    k_zero_counts<<<98, 512>>>();
    k_degree<<<784, 1024>>>(dst);
    k_scan1<<<SCAN_B, 512>>>();
    k_scan2<<<1, 32>>>();
    k_scan3<<<SCAN_B, 512>>>();
    k_scatter<<<784, 1024>>>(src, dst);
    k_sort_buckets<<<(NN + 255) / 256, 256>>>();

    // layer 1
    k_gemm1<<<dim3(2, (NN + 127) / 128), 256>>>(x, W1);
    k_logits1<<<(NN + 7) / 8, 256>>>(al1, ar1);
    k_agg1<<<(NN + 7) / 8, 256>>>(b1);

    // layer 2
    k_gemm2<<<1184, 256>>>(W2, al2, ar2);
    k_agg2<<<(NN + 7) / 8, 256>>>(b2, out);
}

// round 2
// speedup vs baseline: 1.1995x; 1.1995x over previous
#include <cuda_runtime.h>
#include <cuda_bf16.h>

#define NN 50000
#define NE 800000
#define SCAN_B 98          // ceil(50000/512)

// ---------------- scratch (device globals; no allocation allowed) ----------------
__device__ float g_f1[(size_t)NN * 256];   // layer1 projected features
__device__ float g_h1[(size_t)NN * 256];   // layer1 output (post-ELU)
__device__ float g_f2[(size_t)NN * 32];    // layer2 projected features
__device__ float g_el1[NN * 8];
__device__ float g_er1[NN * 8];
__device__ float g_el2[NN];
__device__ float g_er2[NN];
__device__ int   g_offs[NN + 1];
__device__ int   g_cursor[NN];
__device__ int   g_csr_src[NE];
__device__ int   g_partials[SCAN_B + 32];

// ---------------- f32x2 packed-FMA helpers ----------------
__device__ __forceinline__ unsigned long long pk2(float x, float y) {
    unsigned long long r;
    asm("mov.b64 %0, {%1, %2};" : "=l"(r) : "f"(x), "f"(y));
    return r;
}
__device__ __forceinline__ void upk2(unsigned long long v, float& x, float& y) {
    asm("mov.b64 {%0, %1}, %2;" : "=f"(x), "=f"(y) : "l"(v));
}
__device__ __forceinline__ void fma2(unsigned long long& c, unsigned long long a, unsigned long long b) {
    asm("fma.rn.f32x2 %0, %1, %2, %0;" : "+l"(c) : "l"(a), "l"(b));
}

// ---------------- CSR build ----------------
__global__ void k_zero_counts() {
    for (int i = blockIdx.x * blockDim.x + threadIdx.x; i < NN; i += gridDim.x * blockDim.x)
        g_cursor[i] = 0;
}

__global__ void k_degree(const int* __restrict__ dst) {
    for (int e = blockIdx.x * blockDim.x + threadIdx.x; e < NE; e += gridDim.x * blockDim.x)
        atomicAdd(&g_cursor[dst[e]], 1);
}

__global__ void k_scan1() {   // grid SCAN_B, block 512; block-local exclusive scan
    __shared__ int sh[512];
    int t = threadIdx.x;
    int i = blockIdx.x * 512 + t;
    int v = (i < NN) ? g_cursor[i] : 0;
    sh[t] = v;
    __syncthreads();
    #pragma unroll
    for (int o = 1; o < 512; o <<= 1) {
        int add = (t >= o) ? sh[t - o] : 0;
        __syncthreads();
        sh[t] += add;
        __syncthreads();
    }
    if (i < NN) g_offs[i] = sh[t] - v;      // exclusive
    if (t == 511) g_partials[blockIdx.x] = sh[511];
}

__global__ void k_scan2() {   // 1 block of 128 threads: parallel exclusive scan of partials
    __shared__ int sh[128];
    int t = threadIdx.x;
    int v = (t < SCAN_B) ? g_partials[t] : 0;
    sh[t] = v;
    __syncthreads();
    #pragma unroll
    for (int o = 1; o < 128; o <<= 1) {
        int add = (t >= o) ? sh[t - o] : 0;
        __syncthreads();
        sh[t] += add;
        __syncthreads();
    }
    if (t < SCAN_B) g_partials[t] = sh[t] - v;   // exclusive
}

__global__ void k_scan3() {   // add block prefix; copy into cursor
    int i = blockIdx.x * 512 + threadIdx.x;
    if (i < NN) {
        int v = g_offs[i] + g_partials[blockIdx.x];
        g_offs[i] = v;
        g_cursor[i] = v;
    }
    if (i == 0) g_offs[NN] = NE;
}

__global__ void k_scatter(const int* __restrict__ src, const int* __restrict__ dst) {
    for (int e = blockIdx.x * blockDim.x + threadIdx.x; e < NE; e += gridDim.x * blockDim.x) {
        int p = atomicAdd(&g_cursor[dst[e]], 1);
        g_csr_src[p] = src[e];
    }
}

__global__ void k_sort_buckets() {   // deterministic per-bucket order (sort src ascending)
    int n = blockIdx.x * blockDim.x + threadIdx.x;
    if (n >= NN) return;
    int beg = g_offs[n], end = g_offs[n + 1];
    for (int i = beg + 1; i < end; i++) {
        int key = g_csr_src[i];
        int j = i - 1;
        while (j >= beg && g_csr_src[j] > key) { g_csr_src[j + 1] = g_csr_src[j]; j--; }
        g_csr_src[j + 1] = key;
    }
}

// ---------------- GEMM1: f1[50000,256] = X[50000,128] @ W1[128,256] ----------------
// 128x128 tile, BK=16, 256 threads, 8x8 per thread via f32x2; double-buffered smem.
__global__ __launch_bounds__(256, 2) void k_gemm1(const float* __restrict__ A, const float* __restrict__ B) {
    __shared__ float As[2][16][132];
    __shared__ float Bs[2][16][128];
    int tid = threadIdx.x;
    int tx = tid & 15, ty = tid >> 4;
    int bn = blockIdx.x * 128;
    int bm = blockIdx.y * 128;

    // loader coords
    int arow = tid >> 2, ac4 = tid & 3;           // A: 2 chunks (tid, tid+256)
    int arow2 = (tid + 256) >> 2, ac42 = (tid + 256) & 3;
    int bkr = tid >> 5, bc4 = tid & 31;           // B: 2 chunks
    int bkr2 = (tid + 256) >> 5, bc42 = (tid + 256) & 31;

    unsigned long long c[8][4];
    #pragma unroll
    for (int i = 0; i < 8; i++)
        #pragma unroll
        for (int j = 0; j < 4; j++) c[i][j] = 0ull;

    float4 ra0, ra1, rb0, rb1;
    // prologue: load tile 0
    {
        int gr0 = bm + arow, gr1 = bm + arow2;
        ra0 = (gr0 < NN) ? *(const float4*)(A + (size_t)gr0 * 128 + ac4 * 4) : make_float4(0.f,0.f,0.f,0.f);
        ra1 = (gr1 < NN) ? *(const float4*)(A + (size_t)gr1 * 128 + ac42 * 4) : make_float4(0.f,0.f,0.f,0.f);
        rb0 = *(const float4*)(B + (size_t)bkr  * 256 + bn + bc4  * 4);
        rb1 = *(const float4*)(B + (size_t)bkr2 * 256 + bn + bc42 * 4);
        As[0][ac4 * 4 + 0][arow] = ra0.x; As[0][ac4 * 4 + 1][arow] = ra0.y;
        As[0][ac4 * 4 + 2][arow] = ra0.z; As[0][ac4 * 4 + 3][arow] = ra0.w;
        As[0][ac42 * 4 + 0][arow2] = ra1.x; As[0][ac42 * 4 + 1][arow2] = ra1.y;
        As[0][ac42 * 4 + 2][arow2] = ra1.z; As[0][ac42 * 4 + 3][arow2] = ra1.w;
        *(float4*)&Bs[0][bkr][bc4 * 4] = rb0;
        *(float4*)&Bs[0][bkr2][bc42 * 4] = rb1;
    }
    __syncthreads();

    #pragma unroll
    for (int t = 0; t < 8; t++) {
        int cur = t & 1;
        if (t < 7) {
            int kt = (t + 1) * 16;
            int gr0 = bm + arow, gr1 = bm + arow2;
            ra0 = (gr0 < NN) ? *(const float4*)(A + (size_t)gr0 * 128 + kt + ac4 * 4) : make_float4(0.f,0.f,0.f,0.f);
            ra1 = (gr1 < NN) ? *(const float4*)(A + (size_t)gr1 * 128 + kt + ac42 * 4) : make_float4(0.f,0.f,0.f,0.f);
            rb0 = *(const float4*)(B + (size_t)(kt + bkr)  * 256 + bn + bc4  * 4);
            rb1 = *(const float4*)(B + (size_t)(kt + bkr2) * 256 + bn + bc42 * 4);
        }
        #pragma unroll
        for (int k = 0; k < 16; k++) {
            float4 a0 = *(const float4*)&As[cur][k][ty * 4];
            float4 a1 = *(const float4*)&As[cur][k][64 + ty * 4];
            float4 b0 = *(const float4*)&Bs[cur][k][tx * 4];
            float4 b1 = *(const float4*)&Bs[cur][k][64 + tx * 4];
            float av[8] = {a0.x, a0.y, a0.z, a0.w, a1.x, a1.y, a1.z, a1.w};
            unsigned long long bp[4];
            bp[0] = pk2(b0.x, b0.y); bp[1] = pk2(b0.z, b0.w);
            bp[2] = pk2(b1.x, b1.y); bp[3] = pk2(b1.z, b1.w);
            #pragma unroll
            for (int i = 0; i < 8; i++) {
                unsigned long long aa = pk2(av[i], av[i]);
                fma2(c[i][0], aa, bp[0]);
                fma2(c[i][1], aa, bp[1]);
                fma2(c[i][2], aa, bp[2]);
                fma2(c[i][3], aa, bp[3]);
            }
        }
        if (t < 7) {
            int nxt = cur ^ 1;
            As[nxt][ac4 * 4 + 0][arow] = ra0.x; As[nxt][ac4 * 4 + 1][arow] = ra0.y;
            As[nxt][ac4 * 4 + 2][arow] = ra0.z; As[nxt][ac4 * 4 + 3][arow] = ra0.w;
            As[nxt][ac42 * 4 + 0][arow2] = ra1.x; As[nxt][ac42 * 4 + 1][arow2] = ra1.y;
            As[nxt][ac42 * 4 + 2][arow2] = ra1.z; As[nxt][ac42 * 4 + 3][arow2] = ra1.w;
            *(float4*)&Bs[nxt][bkr][bc4 * 4] = rb0;
            *(float4*)&Bs[nxt][bkr2][bc42 * 4] = rb1;
        }
        __syncthreads();
    }

    #pragma unroll
    for (int i = 0; i < 8; i++) {
        int mloc = (i < 4) ? (ty * 4 + i) : (64 + ty * 4 + i - 4);
        int gr = bm + mloc;
        if (gr >= NN) continue;
        float4 lo, hi;
        upk2(c[i][0], lo.x, lo.y); upk2(c[i][1], lo.z, lo.w);
        upk2(c[i][2], hi.x, hi.y); upk2(c[i][3], hi.z, hi.w);
        *(float4*)(g_f1 + (size_t)gr * 256 + bn + tx * 4) = lo;
        *(float4*)(g_f1 + (size_t)gr * 256 + bn + 64 + tx * 4) = hi;
    }
}

// ---------------- layer-1 attention logits: el1/er1 [N,8] (vectorized) ----------------
__global__ __launch_bounds__(256) void k_logits1(const float* __restrict__ al1, const float* __restrict__ ar1) {
    int warp = (blockIdx.x * blockDim.x + threadIdx.x) >> 5;
    int lane = threadIdx.x & 31;
    if (warp >= NN) return;
    const float4* F = (const float4*)g_f1;
    const float4* AL = (const float4*)al1;
    const float4* AR = (const float4*)ar1;
    float4 v0 = F[(size_t)warp * 64 + lane];
    float4 v1 = F[(size_t)warp * 64 + lane + 32];
    float4 l0 = AL[lane], l1 = AL[lane + 32];
    float4 r0 = AR[lane], r1 = AR[lane + 32];
    float pl0 = v0.x * l0.x + v0.y * l0.y + v0.z * l0.z + v0.w * l0.w;
    float pl1 = v1.x * l1.x + v1.y * l1.y + v1.z * l1.z + v1.w * l1.w;
    float pr0 = v0.x * r0.x + v0.y * r0.y + v0.z * r0.z + v0.w * r0.w;
    float pr1 = v1.x * r1.x + v1.y * r1.y + v1.z * r1.z + v1.w * r1.w;
    // reduce within contiguous 8-lane head groups
    #pragma unroll
    for (int o = 1; o < 8; o <<= 1) {
        pl0 += __shfl_xor_sync(0xffffffffu, pl0, o);
        pl1 += __shfl_xor_sync(0xffffffffu, pl1, o);
        pr0 += __shfl_xor_sync(0xffffffffu, pr0, o);
        pr1 += __shfl_xor_sync(0xffffffffu, pr1, o);
    }
    if ((lane & 7) == 0) {
        int h = lane >> 3;
        g_el1[warp * 8 + h] = pl0;     g_el1[warp * 8 + 4 + h] = pl1;
        g_er1[warp * 8 + h] = pr0;     g_er1[warp * 8 + 4 + h] = pr1;
    }
}

__device__ __forceinline__ float lrelu(float e) { return e > 0.f ? e : 0.2f * e; }
__device__ __forceinline__ float elu(float v)   { return v > 0.f ? v : expm1f(v); }

// ---------------- layer-1 aggregation: softmax over incoming edges + ELU ----------------
__global__ __launch_bounds__(256) void k_agg1(const float* __restrict__ b1) {
    int warp = (blockIdx.x * blockDim.x + threadIdx.x) >> 5;
    int lane = threadIdx.x & 31;
    if (warp >= NN) return;
    int n = warp;
    int beg = g_offs[n], end = g_offs[n + 1];
    const float4* B4 = (const float4*)b1;
    float4 bb0 = B4[lane], bb1 = B4[lane + 32];
    float4* H = (float4*)g_h1;

    if (beg == end) {   // empty segment: out = elu(0 + b1)
        float4 o0 = make_float4(elu(bb0.x), elu(bb0.y), elu(bb0.z), elu(bb0.w));
        float4 o1 = make_float4(elu(bb1.x), elu(bb1.y), elu(bb1.z), elu(bb1.w));
        H[(size_t)n * 64 + lane] = o0;
        H[(size_t)n * 64 + lane + 32] = o1;
        return;
    }

    int hmod = lane & 7;
    int h0 = lane >> 3, h1 = 4 + (lane >> 3);
    float er_own = g_er1[n * 8 + hmod];

    // pass 1: per-head max (4 lanes per head)
    float m = -3.402823466e38f;
    for (int i = beg + (lane >> 3); i < end; i += 4) {
        int s = __ldg(&g_csr_src[i]);
        m = fmaxf(m, lrelu(__ldg(&g_el1[s * 8 + hmod]) + er_own));
    }
    m = fmaxf(m, __shfl_xor_sync(0xffffffffu, m, 8));
    m = fmaxf(m, __shfl_xor_sync(0xffffffffu, m, 16));

    // pass 2: 2-edge unrolled accumulation; lanes 0..7 own head weights
    const float4* F = (const float4*)g_f1;
    float4 acc0 = make_float4(0.f, 0.f, 0.f, 0.f);
    float4 acc1 = make_float4(0.f, 0.f, 0.f, 0.f);
    float wsum = 0.f;
    int i = beg;
    for (; i + 2 <= end; i += 2) {
        int s0 = __ldg(&g_csr_src[i]);
        int s1 = __ldg(&g_csr_src[i + 1]);
        float w0 = 0.f, w1 = 0.f;
        if (lane < 8) {
            w0 = __expf(lrelu(__ldg(&g_el1[s0 * 8 + lane]) + er_own) - m);
            w1 = __expf(lrelu(__ldg(&g_el1[s1 * 8 + lane]) + er_own) - m);
            wsum += w0 + w1;
        }
        float4 a00 = F[(size_t)s0 * 64 + lane];
        float4 a01 = F[(size_t)s0 * 64 + lane + 32];
        float4 a10 = F[(size_t)s1 * 64 + lane];
        float4 a11 = F[(size_t)s1 * 64 + lane + 32];
        float wh00 = __shfl_sync(0xffffffffu, w0, h0);
        float wh01 = __shfl_sync(0xffffffffu, w0, h1);
        float wh10 = __shfl_sync(0xffffffffu, w1, h0);
        float wh11 = __shfl_sync(0xffffffffu, w1, h1);
        acc0.x = fmaf(wh00, a00.x, acc0.x); acc0.y = fmaf(wh00, a00.y, acc0.y);
        acc0.z = fmaf(wh00, a00.z, acc0.z); acc0.w = fmaf(wh00, a00.w, acc0.w);
        acc1.x = fmaf(wh01, a01.x, acc1.x); acc1.y = fmaf(wh01, a01.y, acc1.y);
        acc1.z = fmaf(wh01, a01.z, acc1.z); acc1.w = fmaf(wh01, a01.w, acc1.w);
        acc0.x = fmaf(wh10, a10.x, acc0.x); acc0.y = fmaf(wh10, a10.y, acc0.y);
        acc0.z = fmaf(wh10, a10.z, acc0.z); acc0.w = fmaf(wh10, a10.w, acc0.w);
        acc1.x = fmaf(wh11, a11.x, acc1.x); acc1.y = fmaf(wh11, a11.y, acc1.y);
        acc1.z = fmaf(wh11, a11.z, acc1.z); acc1.w = fmaf(wh11, a11.w, acc1.w);
    }
    if (i < end) {
        int s0 = __ldg(&g_csr_src[i]);
        float w0 = 0.f;
        if (lane < 8) {
            w0 = __expf(lrelu(__ldg(&g_el1[s0 * 8 + lane]) + er_own) - m);
            wsum += w0;
        }
        float4 a00 = F[(size_t)s0 * 64 + lane];
        float4 a01 = F[(size_t)s0 * 64 + lane + 32];
        float wh00 = __shfl_sync(0xffffffffu, w0, h0);
        float wh01 = __shfl_sync(0xffffffffu, w0, h1);
        acc0.x = fmaf(wh00, a00.x, acc0.x); acc0.y = fmaf(wh00, a00.y, acc0.y);
        acc0.z = fmaf(wh00, a00.z, acc0.z); acc0.w = fmaf(wh00, a00.w, acc0.w);
        acc1.x = fmaf(wh01, a01.x, acc1.x); acc1.y = fmaf(wh01, a01.y, acc1.y);
        acc1.z = fmaf(wh01, a01.z, acc1.z); acc1.w = fmaf(wh01, a01.w, acc1.w);
    }
    float d0 = __shfl_sync(0xffffffffu, wsum, h0);
    float d1 = __shfl_sync(0xffffffffu, wsum, h1);
    float inv0 = 1.f / d0, inv1 = 1.f / d1;
    float4 o0 = make_float4(elu(acc0.x * inv0 + bb0.x), elu(acc0.y * inv0 + bb0.y),
                            elu(acc0.z * inv0 + bb0.z), elu(acc0.w * inv0 + bb0.w));
    float4 o1 = make_float4(elu(acc1.x * inv1 + bb1.x), elu(acc1.y * inv1 + bb1.y),
                            elu(acc1.z * inv1 + bb1.z), elu(acc1.w * inv1 + bb1.w));
    H[(size_t)n * 64 + lane] = o0;
    H[(size_t)n * 64 + lane + 32] = o1;
}

// ---------------- GEMM2 (fused logits): f2[N,32] = h1 @ W2; el2/er2 ----------------
__global__ __launch_bounds__(256) void k_gemm2(const float* __restrict__ W2,
                                               const float* __restrict__ al2,
                                               const float* __restrict__ ar2) {
    __shared__ float4 sW[64][32];   // sW[k4][c] = W2[(4k4+j)*32 + c]
    __shared__ float sal[32], sar[32];
    int tid = threadIdx.x;
    for (int q = tid; q < 2048; q += 256) {
        int k4 = q >> 5, cc = q & 31;
        sW[k4][cc] = make_float4(W2[(k4 * 4 + 0) * 32 + cc], W2[(k4 * 4 + 1) * 32 + cc],
                                 W2[(k4 * 4 + 2) * 32 + cc], W2[(k4 * 4 + 3) * 32 + cc]);
    }
    if (tid < 32) { sal[tid] = al2[tid]; sar[tid] = ar2[tid]; }
    __syncthreads();

    int lane = tid & 31;
    int warp = (blockIdx.x * blockDim.x + tid) >> 5;
    int nwarps = (gridDim.x * blockDim.x) >> 5;
    for (int n = warp; n < NN; n += nwarps) {
        const float4* hrow = (const float4*)(g_h1 + (size_t)n * 256);
        float acc = 0.f;
        #pragma unroll 16
        for (int k4 = 0; k4 < 64; k4++) {
            float4 hv = hrow[k4];                 // broadcast load
            float4 wv = sW[k4][lane];             // conflict-free LDS.128
            acc = fmaf(hv.x, wv.x, acc);
            acc = fmaf(hv.y, wv.y, acc);
            acc = fmaf(hv.z, wv.z, acc);
            acc = fmaf(hv.w, wv.w, acc);
        }
        g_f2[(size_t)n * 32 + lane] = acc;
        float pl = acc * sal[lane];
        float pr = acc * sar[lane];
        #pragma unroll
        for (int o = 16; o; o >>= 1) {
            pl += __shfl_xor_sync(0xffffffffu, pl, o);
            pr += __shfl_xor_sync(0xffffffffu, pr, o);
        }
        if (lane == 0) { g_el2[n] = pl; g_er2[n] = pr; }
    }
}

// ---------------- layer-2 aggregation -> final output [N,32] ----------------
__global__ __launch_bounds__(256) void k_agg2(const float* __restrict__ b2, float* __restrict__ out) {
    int warp = (blockIdx.x * blockDim.x + threadIdx.x) >> 5;
    int lane = threadIdx.x & 31;
    if (warp >= NN) return;
    int n = warp;
    int beg = g_offs[n], end = g_offs[n + 1];
    float bb = b2[lane];
    if (beg == end) { out[(size_t)n * 32 + lane] = bb; return; }

    float er_own = g_er2[n];
    float m = -3.402823466e38f;
    for (int i = beg + lane; i < end; i += 32) {
        int s = __ldg(&g_csr_src[i]);
        m = fmaxf(m, lrelu(__ldg(&g_el2[s]) + er_own));
    }
    #pragma unroll
    for (int o = 16; o; o >>= 1) m = fmaxf(m, __shfl_xor_sync(0xffffffffu, m, o));

    float acc = 0.f, wsum = 0.f;
    int i = beg;
    for (; i + 2 <= end; i += 2) {
        int s0 = __ldg(&g_csr_src[i]);
        int s1 = __ldg(&g_csr_src[i + 1]);
        float w0 = __expf(lrelu(__ldg(&g_el2[s0]) + er_own) - m);
        float w1 = __expf(lrelu(__ldg(&g_el2[s1]) + er_own) - m);
        wsum += w0 + w1;
        float v0 = __ldg(&g_f2[(size_t)s0 * 32 + lane]);
        float v1 = __ldg(&g_f2[(size_t)s1 * 32 + lane]);
        acc = fmaf(w0, v0, acc);
        acc = fmaf(w1, v1, acc);
    }
    if (i < end) {
        int s0 = __ldg(&g_csr_src[i]);
        float w0 = __expf(lrelu(__ldg(&g_el2[s0]) + er_own) - m);
        wsum += w0;
        acc = fmaf(w0, __ldg(&g_f2[(size_t)s0 * 32 + lane]), acc);
    }
    out[(size_t)n * 32 + lane] = acc / wsum + bb;
}

// ---------------- launch ----------------
extern "C" void kernel_launch(void* const* d_in, const int* in_sizes, int n_in,
                              void* d_out, int out_size) {
    const float* x   = (const float*)d_in[0];
    const int*   src = (const int*)d_in[1];
    const int*   dst = (const int*)d_in[2];
    const float* W1  = (const float*)d_in[3];
    const float* al1 = (const float*)d_in[4];
    const float* ar1 = (const float*)d_in[5];
    const float* b1  = (const float*)d_in[6];
    const float* W2  = (const float*)d_in[7];
    const float* al2 = (const float*)d_in[8];
    const float* ar2 = (const float*)d_in[9];
    const float* b2  = (const float*)d_in[10];
    float* out = (float*)d_out;

    // fork: CSR build (src/dst only) runs concurrently with GEMM1+logits1 (x/W1 only)
    cudaStream_t s2;
    cudaStreamCreateWithFlags(&s2, cudaStreamNonBlocking);
    cudaEvent_t evFork, evJoin;
    cudaEventCreateWithFlags(&evFork, cudaEventDisableTiming);
    cudaEventCreateWithFlags(&evJoin, cudaEventDisableTiming);

    cudaEventRecord(evFork, 0);
    cudaStreamWaitEvent(s2, evFork, 0);

    // branch A (stream s2): CSR build, deterministic per-bucket order
    k_zero_counts<<<98, 512, 0, s2>>>();
    k_degree<<<784, 1024, 0, s2>>>(dst);
    k_scan1<<<SCAN_B, 512, 0, s2>>>();
    k_scan2<<<1, 128, 0, s2>>>();
    k_scan3<<<SCAN_B, 512, 0, s2>>>();
    k_scatter<<<784, 1024, 0, s2>>>(src, dst);
    k_sort_buckets<<<(NN + 255) / 256, 256, 0, s2>>>();
    cudaEventRecord(evJoin, s2);

    // branch B (default stream): layer-1 projection + logits
    k_gemm1<<<dim3(2, (NN + 127) / 128), 256>>>(x, W1);
    k_logits1<<<(NN + 7) / 8, 256>>>(al1, ar1);

    // join
    cudaStreamWaitEvent(0, evJoin, 0);

    k_agg1<<<(NN + 7) / 8, 256>>>(b1);
    k_gemm2<<<1184, 256>>>(W2, al2, ar2);
    k_agg2<<<(NN + 7) / 8, 256>>>(b2, out);

    cudaEventDestroy(evFork);
    cudaEventDestroy(evJoin);
    cudaStreamDestroy(s2);
}

// round 3
// speedup vs baseline: 1.3811x; 1.1514x over previous
#include <cuda_runtime.h>
#include <cuda_bf16.h>

#define NN 50000
#define NE 800000
#define SCAN_B 98          // ceil(50000/512)

// ---------------- scratch (device globals; no allocation allowed) ----------------
__device__ float g_f1[(size_t)NN * 256];   // layer1 projected features
__device__ float g_h1[(size_t)NN * 256];   // layer1 output (post-ELU)
__device__ float g_f2[(size_t)NN * 32];    // layer2 projected features
__device__ float g_el1[NN * 8];
__device__ float g_er1[NN * 8];
__device__ float g_el2[NN];
__device__ float g_er2[NN];
__device__ int   g_offs[NN + 1];
__device__ int   g_cursor[NN];
__device__ int   g_csr_src[NE];
__device__ int   g_partials[SCAN_B + 32];

// ---------------- f32x2 packed-FMA helpers ----------------
__device__ __forceinline__ unsigned long long pk2(float x, float y) {
    unsigned long long r;
    asm("mov.b64 %0, {%1, %2};" : "=l"(r) : "f"(x), "f"(y));
    return r;
}
__device__ __forceinline__ void upk2(unsigned long long v, float& x, float& y) {
    asm("mov.b64 {%0, %1}, %2;" : "=f"(x), "=f"(y) : "l"(v));
}
__device__ __forceinline__ void fma2(unsigned long long& c, unsigned long long a, unsigned long long b) {
    asm("fma.rn.f32x2 %0, %1, %2, %0;" : "+l"(c) : "l"(a), "l"(b));
}

// ---------------- CSR build ----------------
__global__ void k_zero_counts() {
    for (int i = blockIdx.x * blockDim.x + threadIdx.x; i < NN; i += gridDim.x * blockDim.x)
        g_cursor[i] = 0;
}

__global__ void k_degree(const int* __restrict__ dst) {
    for (int e = blockIdx.x * blockDim.x + threadIdx.x; e < NE; e += gridDim.x * blockDim.x)
        atomicAdd(&g_cursor[dst[e]], 1);
}

__global__ void k_scan1() {   // grid SCAN_B, block 512; block-local exclusive scan
    __shared__ int sh[512];
    int t = threadIdx.x;
    int i = blockIdx.x * 512 + t;
    int v = (i < NN) ? g_cursor[i] : 0;
    sh[t] = v;
    __syncthreads();
    #pragma unroll
    for (int o = 1; o < 512; o <<= 1) {
        int add = (t >= o) ? sh[t - o] : 0;
        __syncthreads();
        sh[t] += add;
        __syncthreads();
    }
    if (i < NN) g_offs[i] = sh[t] - v;      // exclusive
    if (t == 511) g_partials[blockIdx.x] = sh[511];
}

__global__ void k_scan2() {   // 1 block of 128 threads: parallel exclusive scan of partials
    __shared__ int sh[128];
    int t = threadIdx.x;
    int v = (t < SCAN_B) ? g_partials[t] : 0;
    sh[t] = v;
    __syncthreads();
    #pragma unroll
    for (int o = 1; o < 128; o <<= 1) {
        int add = (t >= o) ? sh[t - o] : 0;
        __syncthreads();
        sh[t] += add;
        __syncthreads();
    }
    if (t < SCAN_B) g_partials[t] = sh[t] - v;   // exclusive
}

__global__ void k_scan3() {   // add block prefix; copy into cursor
    int i = blockIdx.x * 512 + threadIdx.x;
    if (i < NN) {
        int v = g_offs[i] + g_partials[blockIdx.x];
        g_offs[i] = v;
        g_cursor[i] = v;
    }
    if (i == 0) g_offs[NN] = NE;
}

__global__ void k_scatter(const int* __restrict__ src, const int* __restrict__ dst) {
    for (int e = blockIdx.x * blockDim.x + threadIdx.x; e < NE; e += gridDim.x * blockDim.x) {
        int p = atomicAdd(&g_cursor[dst[e]], 1);
        g_csr_src[p] = src[e];
    }
}

// warp-per-node bitonic sort of each CSR bucket (deterministic ascending src)
__global__ __launch_bounds__(256) void k_sort_buckets() {
    int warp = (blockIdx.x * blockDim.x + threadIdx.x) >> 5;
    int lane = threadIdx.x & 31;
    if (warp >= NN) return;
    int beg = g_offs[warp], end = g_offs[warp + 1];
    int deg = end - beg;
    if (deg <= 1) return;
    if (deg <= 32) {
        int v = (lane < deg) ? g_csr_src[beg + lane] : 0x7fffffff;
        #pragma unroll
        for (int k = 2; k <= 32; k <<= 1) {
            #pragma unroll
            for (int j = k >> 1; j > 0; j >>= 1) {
                int other = __shfl_xor_sync(0xffffffffu, v, j);
                bool up = ((lane & k) == 0);
                bool keepMin = (((lane & j) == 0) == up);
                v = keepMin ? min(v, other) : max(v, other);
            }
        }
        if (lane < deg) g_csr_src[beg + lane] = v;
    } else if (lane == 0) {   // rare (Poisson(16), deg>32): serial insertion sort
        for (int i = beg + 1; i < end; i++) {
            int key = g_csr_src[i];
            int j = i - 1;
            while (j >= beg && g_csr_src[j] > key) { g_csr_src[j + 1] = g_csr_src[j]; j--; }
            g_csr_src[j + 1] = key;
        }
    }
}

// ---------------- GEMM1: f1[50000,256] = X[50000,128] @ W1[128,256] ----------------
// 128x128 tile, BK=16, 256 threads, 8x8 per thread via f32x2; double-buffered smem.
__global__ __launch_bounds__(256, 2) void k_gemm1(const float* __restrict__ A, const float* __restrict__ B) {
    __shared__ float As[2][16][132];
    __shared__ float Bs[2][16][128];
    int tid = threadIdx.x;
    int tx = tid & 15, ty = tid >> 4;
    int bn = blockIdx.x * 128;
    int bm = blockIdx.y * 128;

    int arow = tid >> 2, ac4 = tid & 3;
    int arow2 = (tid + 256) >> 2, ac42 = (tid + 256) & 3;
    int bkr = tid >> 5, bc4 = tid & 31;
    int bkr2 = (tid + 256) >> 5, bc42 = (tid + 256) & 31;

    unsigned long long c[8][4];
    #pragma unroll
    for (int i = 0; i < 8; i++)
        #pragma unroll
        for (int j = 0; j < 4; j++) c[i][j] = 0ull;

    float4 ra0, ra1, rb0, rb1;
    {
        int gr0 = bm + arow, gr1 = bm + arow2;
        ra0 = (gr0 < NN) ? *(const float4*)(A + (size_t)gr0 * 128 + ac4 * 4) : make_float4(0.f,0.f,0.f,0.f);
        ra1 = (gr1 < NN) ? *(const float4*)(A + (size_t)gr1 * 128 + ac42 * 4) : make_float4(0.f,0.f,0.f,0.f);
        rb0 = *(const float4*)(B + (size_t)bkr  * 256 + bn + bc4  * 4);
        rb1 = *(const float4*)(B + (size_t)bkr2 * 256 + bn + bc42 * 4);
        As[0][ac4 * 4 + 0][arow] = ra0.x; As[0][ac4 * 4 + 1][arow] = ra0.y;
        As[0][ac4 * 4 + 2][arow] = ra0.z; As[0][ac4 * 4 + 3][arow] = ra0.w;
        As[0][ac42 * 4 + 0][arow2] = ra1.x; As[0][ac42 * 4 + 1][arow2] = ra1.y;
        As[0][ac42 * 4 + 2][arow2] = ra1.z; As[0][ac42 * 4 + 3][arow2] = ra1.w;
        *(float4*)&Bs[0][bkr][bc4 * 4] = rb0;
        *(float4*)&Bs[0][bkr2][bc42 * 4] = rb1;
    }
    __syncthreads();

    #pragma unroll
    for (int t = 0; t < 8; t++) {
        int cur = t & 1;
        if (t < 7) {
            int kt = (t + 1) * 16;
            int gr0 = bm + arow, gr1 = bm + arow2;
            ra0 = (gr0 < NN) ? *(const float4*)(A + (size_t)gr0 * 128 + kt + ac4 * 4) : make_float4(0.f,0.f,0.f,0.f);
            ra1 = (gr1 < NN) ? *(const float4*)(A + (size_t)gr1 * 128 + kt + ac42 * 4) : make_float4(0.f,0.f,0.f,0.f);
            rb0 = *(const float4*)(B + (size_t)(kt + bkr)  * 256 + bn + bc4  * 4);
            rb1 = *(const float4*)(B + (size_t)(kt + bkr2) * 256 + bn + bc42 * 4);
        }
        #pragma unroll
        for (int k = 0; k < 16; k++) {
            float4 a0 = *(const float4*)&As[cur][k][ty * 4];
            float4 a1 = *(const float4*)&As[cur][k][64 + ty * 4];
            float4 b0 = *(const float4*)&Bs[cur][k][tx * 4];
            float4 b1 = *(const float4*)&Bs[cur][k][64 + tx * 4];
            float av[8] = {a0.x, a0.y, a0.z, a0.w, a1.x, a1.y, a1.z, a1.w};
            unsigned long long bp[4];
            bp[0] = pk2(b0.x, b0.y); bp[1] = pk2(b0.z, b0.w);
            bp[2] = pk2(b1.x, b1.y); bp[3] = pk2(b1.z, b1.w);
            #pragma unroll
            for (int i = 0; i < 8; i++) {
                unsigned long long aa = pk2(av[i], av[i]);
                fma2(c[i][0], aa, bp[0]);
                fma2(c[i][1], aa, bp[1]);
                fma2(c[i][2], aa, bp[2]);
                fma2(c[i][3], aa, bp[3]);
            }
        }
        if (t < 7) {
            int nxt = cur ^ 1;
            As[nxt][ac4 * 4 + 0][arow] = ra0.x; As[nxt][ac4 * 4 + 1][arow] = ra0.y;
            As[nxt][ac4 * 4 + 2][arow] = ra0.z; As[nxt][ac4 * 4 + 3][arow] = ra0.w;
            As[nxt][ac42 * 4 + 0][arow2] = ra1.x; As[nxt][ac42 * 4 + 1][arow2] = ra1.y;
            As[nxt][ac42 * 4 + 2][arow2] = ra1.z; As[nxt][ac42 * 4 + 3][arow2] = ra1.w;
            *(float4*)&Bs[nxt][bkr][bc4 * 4] = rb0;
            *(float4*)&Bs[nxt][bkr2][bc42 * 4] = rb1;
        }
        __syncthreads();
    }

    #pragma unroll
    for (int i = 0; i < 8; i++) {
        int mloc = (i < 4) ? (ty * 4 + i) : (64 + ty * 4 + i - 4);
        int gr = bm + mloc;
        if (gr >= NN) continue;
        float4 lo, hi;
        upk2(c[i][0], lo.x, lo.y); upk2(c[i][1], lo.z, lo.w);
        upk2(c[i][2], hi.x, hi.y); upk2(c[i][3], hi.z, hi.w);
        *(float4*)(g_f1 + (size_t)gr * 256 + bn + tx * 4) = lo;
        *(float4*)(g_f1 + (size_t)gr * 256 + bn + 64 + tx * 4) = hi;
    }
}

// ---------------- layer-1 attention logits: el1/er1 [N,8] (vectorized) ----------------
__global__ __launch_bounds__(256) void k_logits1(const float* __restrict__ al1, const float* __restrict__ ar1) {
    int warp = (blockIdx.x * blockDim.x + threadIdx.x) >> 5;
    int lane = threadIdx.x & 31;
    if (warp >= NN) return;
    const float4* F = (const float4*)g_f1;
    const float4* AL = (const float4*)al1;
    const float4* AR = (const float4*)ar1;
    float4 v0 = F[(size_t)warp * 64 + lane];
    float4 v1 = F[(size_t)warp * 64 + lane + 32];
    float4 l0 = AL[lane], l1 = AL[lane + 32];
    float4 r0 = AR[lane], r1 = AR[lane + 32];
    float pl0 = v0.x * l0.x + v0.y * l0.y + v0.z * l0.z + v0.w * l0.w;
    float pl1 = v1.x * l1.x + v1.y * l1.y + v1.z * l1.z + v1.w * l1.w;
    float pr0 = v0.x * r0.x + v0.y * r0.y + v0.z * r0.z + v0.w * r0.w;
    float pr1 = v1.x * r1.x + v1.y * r1.y + v1.z * r1.z + v1.w * r1.w;
    #pragma unroll
    for (int o = 1; o < 8; o <<= 1) {
        pl0 += __shfl_xor_sync(0xffffffffu, pl0, o);
        pl1 += __shfl_xor_sync(0xffffffffu, pl1, o);
        pr0 += __shfl_xor_sync(0xffffffffu, pr0, o);
        pr1 += __shfl_xor_sync(0xffffffffu, pr1, o);
    }
    if ((lane & 7) == 0) {
        int h = lane >> 3;
        g_el1[warp * 8 + h] = pl0;     g_el1[warp * 8 + 4 + h] = pl1;
        g_er1[warp * 8 + h] = pr0;     g_er1[warp * 8 + 4 + h] = pr1;
    }
}

__device__ __forceinline__ float lrelu(float e) { return e > 0.f ? e : 0.2f * e; }
__device__ __forceinline__ float elu(float v)   { return v > 0.f ? v : expm1f(v); }

// ---------------- layer-1 aggregation: softmax over incoming edges + ELU ----------------
__global__ __launch_bounds__(256) void k_agg1(const float* __restrict__ b1) {
    int warp = (blockIdx.x * blockDim.x + threadIdx.x) >> 5;
    int lane = threadIdx.x & 31;
    if (warp >= NN) return;
    int n = warp;
    int beg = g_offs[n], end = g_offs[n + 1];
    const float4* B4 = (const float4*)b1;
    float4 bb0 = B4[lane], bb1 = B4[lane + 32];
    float4* H = (float4*)g_h1;

    if (beg == end) {
        float4 o0 = make_float4(elu(bb0.x), elu(bb0.y), elu(bb0.z), elu(bb0.w));
        float4 o1 = make_float4(elu(bb1.x), elu(bb1.y), elu(bb1.z), elu(bb1.w));
        H[(size_t)n * 64 + lane] = o0;
        H[(size_t)n * 64 + lane + 32] = o1;
        return;
    }

    int hmod = lane & 7;
    int h0 = lane >> 3, h1 = 4 + (lane >> 3);
    float er_own = g_er1[n * 8 + hmod];

    float m = -3.402823466e38f;
    for (int i = beg + (lane >> 3); i < end; i += 4) {
        int s = __ldg(&g_csr_src[i]);
        m = fmaxf(m, lrelu(__ldg(&g_el1[s * 8 + hmod]) + er_own));
    }
    m = fmaxf(m, __shfl_xor_sync(0xffffffffu, m, 8));
    m = fmaxf(m, __shfl_xor_sync(0xffffffffu, m, 16));

    const float4* F = (const float4*)g_f1;
    float4 acc0 = make_float4(0.f, 0.f, 0.f, 0.f);
    float4 acc1 = make_float4(0.f, 0.f, 0.f, 0.f);
    float wsum = 0.f;
    int i = beg;
    for (; i + 2 <= end; i += 2) {
        int s0 = __ldg(&g_csr_src[i]);
        int s1 = __ldg(&g_csr_src[i + 1]);
        float w0 = 0.f, w1 = 0.f;
        if (lane < 8) {
            w0 = __expf(lrelu(__ldg(&g_el1[s0 * 8 + lane]) + er_own) - m);
            w1 = __expf(lrelu(__ldg(&g_el1[s1 * 8 + lane]) + er_own) - m);
            wsum += w0 + w1;
        }
        float4 a00 = F[(size_t)s0 * 64 + lane];
        float4 a01 = F[(size_t)s0 * 64 + lane + 32];
        float4 a10 = F[(size_t)s1 * 64 + lane];
        float4 a11 = F[(size_t)s1 * 64 + lane + 32];
        float wh00 = __shfl_sync(0xffffffffu, w0, h0);
        float wh01 = __shfl_sync(0xffffffffu, w0, h1);
        float wh10 = __shfl_sync(0xffffffffu, w1, h0);
        float wh11 = __shfl_sync(0xffffffffu, w1, h1);
        acc0.x = fmaf(wh00, a00.x, acc0.x); acc0.y = fmaf(wh00, a00.y, acc0.y);
        acc0.z = fmaf(wh00, a00.z, acc0.z); acc0.w = fmaf(wh00, a00.w, acc0.w);
        acc1.x = fmaf(wh01, a01.x, acc1.x); acc1.y = fmaf(wh01, a01.y, acc1.y);
        acc1.z = fmaf(wh01, a01.z, acc1.z); acc1.w = fmaf(wh01, a01.w, acc1.w);
        acc0.x = fmaf(wh10, a10.x, acc0.x); acc0.y = fmaf(wh10, a10.y, acc0.y);
        acc0.z = fmaf(wh10, a10.z, acc0.z); acc0.w = fmaf(wh10, a10.w, acc0.w);
        acc1.x = fmaf(wh11, a11.x, acc1.x); acc1.y = fmaf(wh11, a11.y, acc1.y);
        acc1.z = fmaf(wh11, a11.z, acc1.z); acc1.w = fmaf(wh11, a11.w, acc1.w);
    }
    if (i < end) {
        int s0 = __ldg(&g_csr_src[i]);
        float w0 = 0.f;
        if (lane < 8) {
            w0 = __expf(lrelu(__ldg(&g_el1[s0 * 8 + lane]) + er_own) - m);
            wsum += w0;
        }
        float4 a00 = F[(size_t)s0 * 64 + lane];
        float4 a01 = F[(size_t)s0 * 64 + lane + 32];
        float wh00 = __shfl_sync(0xffffffffu, w0, h0);
        float wh01 = __shfl_sync(0xffffffffu, w0, h1);
        acc0.x = fmaf(wh00, a00.x, acc0.x); acc0.y = fmaf(wh00, a00.y, acc0.y);
        acc0.z = fmaf(wh00, a00.z, acc0.z); acc0.w = fmaf(wh00, a00.w, acc0.w);
        acc1.x = fmaf(wh01, a01.x, acc1.x); acc1.y = fmaf(wh01, a01.y, acc1.y);
        acc1.z = fmaf(wh01, a01.z, acc1.z); acc1.w = fmaf(wh01, a01.w, acc1.w);
    }
    float d0 = __shfl_sync(0xffffffffu, wsum, h0);
    float d1 = __shfl_sync(0xffffffffu, wsum, h1);
    float inv0 = 1.f / d0, inv1 = 1.f / d1;
    float4 o0 = make_float4(elu(acc0.x * inv0 + bb0.x), elu(acc0.y * inv0 + bb0.y),
                            elu(acc0.z * inv0 + bb0.z), elu(acc0.w * inv0 + bb0.w));
    float4 o1 = make_float4(elu(acc1.x * inv1 + bb1.x), elu(acc1.y * inv1 + bb1.y),
                            elu(acc1.z * inv1 + bb1.z), elu(acc1.w * inv1 + bb1.w));
    H[(size_t)n * 64 + lane] = o0;
    H[(size_t)n * 64 + lane + 32] = o1;
}

// ---------------- GEMM2 (fused logits): f2[N,32] = h1 @ W2; el2/er2 ----------------
// Each warp processes a PAIR of nodes; accumulator packs (nodeA, nodeB) via f32x2.
__global__ __launch_bounds__(256) void k_gemm2(const float* __restrict__ W2,
                                               const float* __restrict__ al2,
                                               const float* __restrict__ ar2) {
    __shared__ float4 sW[64][32];   // sW[k4][c] = W2[(4k4+j)*32 + c]
    __shared__ float sal[32], sar[32];
    int tid = threadIdx.x;
    for (int q = tid; q < 2048; q += 256) {
        int k4 = q >> 5, cc = q & 31;
        sW[k4][cc] = make_float4(W2[(k4 * 4 + 0) * 32 + cc], W2[(k4 * 4 + 1) * 32 + cc],
                                 W2[(k4 * 4 + 2) * 32 + cc], W2[(k4 * 4 + 3) * 32 + cc]);
    }
    if (tid < 32) { sal[tid] = al2[tid]; sar[tid] = ar2[tid]; }
    __syncthreads();

    int lane = tid & 31;
    int warp = (blockIdx.x * blockDim.x + tid) >> 5;
    int nwarps = (gridDim.x * blockDim.x) >> 5;
    for (int n = warp * 2; n < NN; n += nwarps * 2) {
        const float4* hA = (const float4*)(g_h1 + (size_t)n * 256);
        const float4* hB = (const float4*)(g_h1 + (size_t)(n + 1) * 256);   // NN even -> n+1 valid
        unsigned long long acc = 0ull;
        #pragma unroll 16
        for (int k4 = 0; k4 < 64; k4++) {
            float4 a = hA[k4];
            float4 b = hB[k4];
            float4 wv = sW[k4][lane];
            fma2(acc, pk2(a.x, b.x), pk2(wv.x, wv.x));
            fma2(acc, pk2(a.y, b.y), pk2(wv.y, wv.y));
            fma2(acc, pk2(a.z, b.z), pk2(wv.z, wv.z));
            fma2(acc, pk2(a.w, b.w), pk2(wv.w, wv.w));
        }
        float accA, accB;
        upk2(acc, accA, accB);
        g_f2[(size_t)n * 32 + lane] = accA;
        g_f2[(size_t)(n + 1) * 32 + lane] = accB;
        float plA = accA * sal[lane], prA = accA * sar[lane];
        float plB = accB * sal[lane], prB = accB * sar[lane];
        #pragma unroll
        for (int o = 16; o; o >>= 1) {
            plA += __shfl_xor_sync(0xffffffffu, plA, o);
            prA += __shfl_xor_sync(0xffffffffu, prA, o);
            plB += __shfl_xor_sync(0xffffffffu, plB, o);
            prB += __shfl_xor_sync(0xffffffffu, prB, o);
        }
        if (lane == 0) {
            g_el2[n] = plA; g_er2[n] = prA;
            g_el2[n + 1] = plB; g_er2[n + 1] = prB;
        }
    }
}

// ---------------- layer-2 aggregation -> final output [N,32] ----------------
__global__ __launch_bounds__(256) void k_agg2(const float* __restrict__ b2, float* __restrict__ out) {
    int warp = (blockIdx.x * blockDim.x + threadIdx.x) >> 5;
    int lane = threadIdx.x & 31;
    if (warp >= NN) return;
    int n = warp;
    int beg = g_offs[n], end = g_offs[n + 1];
    float bb = b2[lane];
    if (beg == end) { out[(size_t)n * 32 + lane] = bb; return; }

    float er_own = g_er2[n];
    float m = -3.402823466e38f;
    for (int i = beg + lane; i < end; i += 32) {
        int s = __ldg(&g_csr_src[i]);
        m = fmaxf(m, lrelu(__ldg(&g_el2[s]) + er_own));
    }
    #pragma unroll
    for (int o = 16; o; o >>= 1) m = fmaxf(m, __shfl_xor_sync(0xffffffffu, m, o));

    float acc = 0.f, wsum = 0.f;
    int i = beg;
    for (; i + 2 <= end; i += 2) {
        int s0 = __ldg(&g_csr_src[i]);
        int s1 = __ldg(&g_csr_src[i + 1]);
        float w0 = __expf(lrelu(__ldg(&g_el2[s0]) + er_own) - m);
        float w1 = __expf(lrelu(__ldg(&g_el2[s1]) + er_own) - m);
        wsum += w0 + w1;
        float v0 = __ldg(&g_f2[(size_t)s0 * 32 + lane]);
        float v1 = __ldg(&g_f2[(size_t)s1 * 32 + lane]);
        acc = fmaf(w0, v0, acc);
        acc = fmaf(w1, v1, acc);
    }
    if (i < end) {
        int s0 = __ldg(&g_csr_src[i]);
        float w0 = __expf(lrelu(__ldg(&g_el2[s0]) + er_own) - m);
        wsum += w0;
        acc = fmaf(w0, __ldg(&g_f2[(size_t)s0 * 32 + lane]), acc);
    }
    out[(size_t)n * 32 + lane] = acc / wsum + bb;
}

// ---------------- launch ----------------
extern "C" void kernel_launch(void* const* d_in, const int* in_sizes, int n_in,
                              void* d_out, int out_size) {
    const float* x   = (const float*)d_in[0];
    const int*   src = (const int*)d_in[1];
    const int*   dst = (const int*)d_in[2];
    const float* W1  = (const float*)d_in[3];
    const float* al1 = (const float*)d_in[4];
    const float* ar1 = (const float*)d_in[5];
    const float* b1  = (const float*)d_in[6];
    const float* W2  = (const float*)d_in[7];
    const float* al2 = (const float*)d_in[8];
    const float* ar2 = (const float*)d_in[9];
    const float* b2  = (const float*)d_in[10];
    float* out = (float*)d_out;

    // fork: CSR build (src/dst only) runs concurrently with GEMM1+logits1 (x/W1 only)
    cudaStream_t s2;
    cudaStreamCreateWithFlags(&s2, cudaStreamNonBlocking);
    cudaEvent_t evFork, evJoin;
    cudaEventCreateWithFlags(&evFork, cudaEventDisableTiming);
    cudaEventCreateWithFlags(&evJoin, cudaEventDisableTiming);

    cudaEventRecord(evFork, 0);
    cudaStreamWaitEvent(s2, evFork, 0);

    // branch A (stream s2): CSR build, deterministic per-bucket order
    k_zero_counts<<<98, 512, 0, s2>>>();
    k_degree<<<784, 1024, 0, s2>>>(dst);
    k_scan1<<<SCAN_B, 512, 0, s2>>>();
    k_scan2<<<1, 128, 0, s2>>>();
    k_scan3<<<SCAN_B, 512, 0, s2>>>();
    k_scatter<<<784, 1024, 0, s2>>>(src, dst);
    k_sort_buckets<<<(NN * 32 + 255) / 256, 256, 0, s2>>>();
    cudaEventRecord(evJoin, s2);

    // branch B (default stream): layer-1 projection + logits
    k_gemm1<<<dim3(2, (NN + 127) / 128), 256>>>(x, W1);
    k_logits1<<<(NN + 7) / 8, 256>>>(al1, ar1);

    // join
    cudaStreamWaitEvent(0, evJoin, 0);

    k_agg1<<<(NN + 7) / 8, 256>>>(b1);
    k_gemm2<<<1184, 256>>>(W2, al2, ar2);
    k_agg2<<<(NN + 7) / 8, 256>>>(b2, out);

    cudaEventDestroy(evFork);
    cudaEventDestroy(evJoin);
    cudaStreamDestroy(s2);
}